// round 4
// baseline (speedup 1.0000x reference)
#include <cuda_runtime.h>
#include <cuda_bf16.h>
#include <math.h>

// Problem constants
#define BB 8
#define NN 4096
#define CC 512
#define NH 8
#define HD 64
#define QKV_N (3 * CC)   // 1536
#define M_TOT (BB * NN)  // 32768

// Scratch (device globals; no runtime allocation allowed)
__device__ float g_xp [ (size_t)M_TOT * CC ];     // x + interp(pos)        64 MB
__device__ float g_qkv[ (size_t)M_TOT * QKV_N ];  // qkv activations       192 MB
__device__ float g_ctx[ (size_t)M_TOT * CC ];     // attention ctx (remapped) 64 MB

// ---------------------------------------------------------------------------
// Kernel 1: xp[b,n,c] = x[b,n,c] + 0.5*(pos32[8n+3,c] + pos32[8n+4,c])
// (linear interp 32768 -> 4096: coords = 8n+3.5 exactly -> constant 0.5/0.5)
// ---------------------------------------------------------------------------
__global__ __launch_bounds__(256) void pos_add_kernel(
    const float* __restrict__ x, const float* __restrict__ pos32,
    float* __restrict__ xp)
{
    int idx = blockIdx.x * blockDim.x + threadIdx.x;  // float4 index
    int c4 = idx & (CC / 4 - 1);       // 0..127
    int bn = idx >> 7;                 // 0..32767
    int n  = bn & (NN - 1);

    float4 xv = reinterpret_cast<const float4*>(x)[idx];
    const float4* p = reinterpret_cast<const float4*>(pos32) +
                      (size_t)(8 * n + 3) * (CC / 4) + c4;
    float4 a = p[0];
    float4 b = p[CC / 4];  // row 8n+4
    xv.x += 0.5f * (a.x + b.x);
    xv.y += 0.5f * (a.y + b.y);
    xv.z += 0.5f * (a.z + b.z);
    xv.w += 0.5f * (a.w + b.w);
    reinterpret_cast<float4*>(xp)[idx] = xv;
}

// ---------------------------------------------------------------------------
// Kernel 2/4: FP32 SGEMM + bias.  C[M,N] = A[M,K] @ B[K,N] + bias[N]
// 128x128 block tile, BK=8, 256 threads, 8x8 per-thread, double-buffered smem.
// M,N multiples of 128; K multiple of 8 (exact here: no bounds checks).
// ---------------------------------------------------------------------------
#define BM 128
#define BN 128
#define BK 8

__global__ __launch_bounds__(256) void sgemm_bias_kernel(
    const float* __restrict__ A, const float* __restrict__ Bm,
    const float* __restrict__ bias, float* __restrict__ C,
    int M, int N, int K)
{
    __shared__ float As[2][BK][BM];
    __shared__ float Bs[2][BK][BN];

    const int tid = threadIdx.x;
    const int bx = blockIdx.x;   // N tile (fastest -> blocks sharing A tile run together)
    const int by = blockIdx.y;   // M tile

    const float* Ablk = A + (size_t)by * BM * K;
    const float* Bblk = Bm + (size_t)bx * BN;

    const int a_row = tid >> 1;           // 0..127
    const int a_col = (tid & 1) << 2;     // 0 or 4
    const int b_row = tid >> 5;           // 0..7
    const int b_col = (tid & 31) << 2;    // 0..124

    const int tx = tid & 15;
    const int ty = tid >> 4;

    float acc[8][8];
#pragma unroll
    for (int i = 0; i < 8; ++i)
#pragma unroll
        for (int j = 0; j < 8; ++j) acc[i][j] = 0.f;

    // preload tile 0
    float4 a_reg = *reinterpret_cast<const float4*>(Ablk + (size_t)a_row * K + a_col);
    float4 b_reg = *reinterpret_cast<const float4*>(Bblk + (size_t)b_row * N + b_col);
    As[0][a_col + 0][a_row] = a_reg.x;
    As[0][a_col + 1][a_row] = a_reg.y;
    As[0][a_col + 2][a_row] = a_reg.z;
    As[0][a_col + 3][a_row] = a_reg.w;
    *reinterpret_cast<float4*>(&Bs[0][b_row][b_col]) = b_reg;
    __syncthreads();

    const int nk = K / BK;
    int buf = 0;
    for (int t = 0; t < nk; ++t) {
        const bool has_next = (t + 1) < nk;
        if (has_next) {
            const int k0 = (t + 1) * BK;
            a_reg = *reinterpret_cast<const float4*>(Ablk + (size_t)a_row * K + k0 + a_col);
            b_reg = *reinterpret_cast<const float4*>(Bblk + (size_t)(k0 + b_row) * N + b_col);
        }
        const float* __restrict__ asb = &As[buf][0][0];
        const float* __restrict__ bsb = &Bs[buf][0][0];
#pragma unroll
        for (int kk = 0; kk < BK; ++kk) {
            float af[8], bf[8];
            reinterpret_cast<float4&>(af[0]) =
                *reinterpret_cast<const float4*>(asb + kk * BM + ty * 4);
            reinterpret_cast<float4&>(af[4]) =
                *reinterpret_cast<const float4*>(asb + kk * BM + 64 + ty * 4);
            reinterpret_cast<float4&>(bf[0]) =
                *reinterpret_cast<const float4*>(bsb + kk * BN + tx * 4);
            reinterpret_cast<float4&>(bf[4]) =
                *reinterpret_cast<const float4*>(bsb + kk * BN + 64 + tx * 4);
#pragma unroll
            for (int i = 0; i < 8; ++i)
#pragma unroll
                for (int j = 0; j < 8; ++j)
                    acc[i][j] = fmaf(af[i], bf[j], acc[i][j]);
        }
        if (has_next) {
            const int nb = buf ^ 1;
            As[nb][a_col + 0][a_row] = a_reg.x;
            As[nb][a_col + 1][a_row] = a_reg.y;
            As[nb][a_col + 2][a_row] = a_reg.z;
            As[nb][a_col + 3][a_row] = a_reg.w;
            *reinterpret_cast<float4*>(&Bs[nb][b_row][b_col]) = b_reg;
            __syncthreads();
            buf = nb;
        }
    }

    // epilogue
#pragma unroll
    for (int ii = 0; ii < 8; ++ii) {
        const int row = (ii < 4) ? (ty * 4 + ii) : (64 + ty * 4 + ii - 4);
        const size_t off = (size_t)(by * BM + row) * N;
#pragma unroll
        for (int jg = 0; jg < 2; ++jg) {
            const int col = bx * BN + jg * 64 + tx * 4;
            const float4 bv = *reinterpret_cast<const float4*>(bias + col);
            float4 o;
            o.x = acc[ii][jg * 4 + 0] + bv.x;
            o.y = acc[ii][jg * 4 + 1] + bv.y;
            o.z = acc[ii][jg * 4 + 2] + bv.z;
            o.w = acc[ii][jg * 4 + 3] + bv.w;
            *reinterpret_cast<float4*>(C + off + col) = o;
        }
    }
}

// ---------------------------------------------------------------------------
// Kernel 3: per-token attention over heads (8x8 softmax, d=64), one warp/token.
// Writes ctx in the reference's transposed layout:
//   ctx[b, h*512 + n/8, (n%8)*64 + d] = O[b,n,h,d]
// so the proj GEMM consumes a plain row-major [32768, 512] matrix.
// ---------------------------------------------------------------------------
#define QK_PITCH 68  // 64 + 4 pad: conflict-free strided row reads

__global__ __launch_bounds__(256) void attn_kernel(
    const float* __restrict__ qkv, float* __restrict__ ctx)
{
    __shared__ float qs[8][NH * QK_PITCH];
    __shared__ float ks[8][NH * QK_PITCH];
    __shared__ float ps[8][NH * NH];

    const int warp = threadIdx.x >> 5;
    const int lane = threadIdx.x & 31;
    const int token = blockIdx.x * 8 + warp;  // 0..32767
    const int b = token >> 12;
    const int n = token & (NN - 1);

    const float* base = qkv + (size_t)token * QKV_N;
    float* const qw = qs[warp];
    float* const kw = ks[warp];
    float* const pw = ps[warp];

    // load q,k (512 floats each) into padded smem
#pragma unroll
    for (int it = 0; it < 16; ++it) {
        const int idx = lane + it * 32;
        const int r = idx >> 6, t = idx & 63;
        qw[r * QK_PITCH + t] = base[idx];
        kw[r * QK_PITCH + t] = base[512 + idx];
    }
    __syncwarp();

    // S[i][j] = q_i . k_j / 8 ;  lane owns (i0,j0) and (i0+4,j0)
    const int i0 = lane >> 3;       // rows 0..3
    const int j0 = lane & 7;        // cols 0..7
    const float* qr0 = qw + i0 * QK_PITCH;
    const float* qr1 = qr0 + 4 * QK_PITCH;
    const float* kr  = kw + j0 * QK_PITCH;
    float s0 = 0.f, s1 = 0.f;
#pragma unroll
    for (int t = 0; t < HD; ++t) {
        const float kv = kr[t];
        s0 = fmaf(qr0[t], kv, s0);
        s1 = fmaf(qr1[t], kv, s1);
    }
    s0 *= 0.125f;  // 1/sqrt(64)
    s1 *= 0.125f;

    // softmax over j within each 8-lane group (same row i)
    float m0 = s0, m1 = s1;
#pragma unroll
    for (int off = 1; off < 8; off <<= 1) {
        m0 = fmaxf(m0, __shfl_xor_sync(0xffffffffu, m0, off));
        m1 = fmaxf(m1, __shfl_xor_sync(0xffffffffu, m1, off));
    }
    float p0 = __expf(s0 - m0);
    float p1 = __expf(s1 - m1);
    float sum0 = p0, sum1 = p1;
#pragma unroll
    for (int off = 1; off < 8; off <<= 1) {
        sum0 += __shfl_xor_sync(0xffffffffu, sum0, off);
        sum1 += __shfl_xor_sync(0xffffffffu, sum1, off);
    }
    pw[i0 * 8 + j0] = p0 / sum0;
    pw[(i0 + 4) * 8 + j0] = p1 / sum1;
    __syncwarp();

    // O[i][d] = sum_j P[i][j] * v[j][d]; lane handles d=lane and d=lane+32
    const float* vbase = base + 1024;
    const size_t obase = (size_t)b * NN * CC;
    const int nlo = n >> 3;        // n/8
    const int csub = (n & 7) * HD; // (n%8)*64
#pragma unroll
    for (int dd = 0; dd < 2; ++dd) {
        const int d = lane + dd * 32;
        float vv[NH];
#pragma unroll
        for (int j = 0; j < NH; ++j) vv[j] = vbase[j * HD + d];
#pragma unroll
        for (int i = 0; i < NH; ++i) {
            float o = 0.f;
#pragma unroll
            for (int j = 0; j < NH; ++j) o = fmaf(pw[i * 8 + j], vv[j], o);
            ctx[obase + (size_t)(i * 512 + nlo) * CC + csub + d] = o;
        }
    }
}

// ---------------------------------------------------------------------------
// Launch
// ---------------------------------------------------------------------------
extern "C" void kernel_launch(void* const* d_in, const int* in_sizes, int n_in,
                              void* d_out, int out_size)
{
    const float* x      = (const float*)d_in[0];
    const float* pos32  = (const float*)d_in[1];
    const float* w_qkv  = (const float*)d_in[2];
    const float* b_qkv  = (const float*)d_in[3];
    const float* w_proj = (const float*)d_in[4];
    const float* b_proj = (const float*)d_in[5];
    float* out = (float*)d_out;

    float *xp, *qkv, *ctx;
    cudaGetSymbolAddress((void**)&xp,  g_xp);
    cudaGetSymbolAddress((void**)&qkv, g_qkv);
    cudaGetSymbolAddress((void**)&ctx, g_ctx);

    // 1) pos interp + add
    {
        const int total4 = M_TOT * CC / 4;  // 4,194,304
        pos_add_kernel<<<total4 / 256, 256>>>(x, pos32, xp);
    }
    // 2) QKV GEMM: (32768x512) @ (512x1536) + b_qkv
    {
        dim3 grid(QKV_N / BN, M_TOT / BM);
        sgemm_bias_kernel<<<grid, 256>>>(xp, w_qkv, b_qkv, qkv, M_TOT, QKV_N, CC);
    }
    // 3) per-token attention over heads
    {
        attn_kernel<<<M_TOT / 8, 256>>>(qkv, ctx);
    }
    // 4) proj GEMM: (32768x512) @ (512x512) + b_proj -> out
    {
        dim3 grid(CC / BN, M_TOT / BM);
        sgemm_bias_kernel<<<grid, 256>>>(ctx, w_proj, b_proj, out, M_TOT, CC, CC);
    }
}

// round 11
// speedup vs baseline: 2.2739x; 2.2739x over previous
#include <cuda_runtime.h>
#include <cuda_bf16.h>
#include <math.h>
#include <cstdint>

// Problem constants
#define BB 8
#define NN 4096
#define CC 512
#define NH 8
#define HD 64
#define QKV_N (3 * CC)   // 1536
#define M_TOT (BB * NN)  // 32768
#define KST 1024         // stored K: [h | l] compact split
#define KLOG 1536        // logical K: hh + hl + lh = 24 chunks of 64

// ---------------------------------------------------------------------------
// Scratch (device globals; no runtime allocation allowed)
// ---------------------------------------------------------------------------
__device__ __nv_bfloat16 g_x2 [(size_t)M_TOT * KST];    // A' for QKV   64 MB
__device__ float         g_qkv[(size_t)M_TOT * QKV_N];  //             192 MB
__device__ __nv_bfloat16 g_c2 [(size_t)M_TOT * KST];    // A' for proj  64 MB
__device__ __nv_bfloat16 g_wq2[(size_t)QKV_N * KST];    // B' qkv       3 MB
__device__ __nv_bfloat16 g_wp2[(size_t)CC * KST];       // B' proj      1 MB

// ---------------------------------------------------------------------------
// Baseline-PTX tensor helpers (compute_103-safe: mma.sync / ldmatrix / cp.async)
// ---------------------------------------------------------------------------
__device__ __forceinline__ uint32_t smem_u32(const void* p) {
    uint32_t a;
    asm("{ .reg .u64 t; cvta.to.shared.u64 t, %1; cvt.u32.u64 %0, t; }"
        : "=r"(a) : "l"(p));
    return a;
}
__device__ __forceinline__ void cp16(uint32_t dst, const void* src) {
    asm volatile("cp.async.cg.shared.global [%0], [%1], 16;"
                 :: "r"(dst), "l"(src));
}
#define CP_COMMIT() asm volatile("cp.async.commit_group;" ::: "memory")
#define CP_WAIT(n)  asm volatile("cp.async.wait_group %0;" :: "n"(n) : "memory")

__device__ __forceinline__ void ldsm_x4(uint32_t& r0, uint32_t& r1,
                                        uint32_t& r2, uint32_t& r3,
                                        uint32_t addr) {
    asm volatile("ldmatrix.sync.aligned.m8n8.x4.shared.b16 {%0,%1,%2,%3}, [%4];"
                 : "=r"(r0), "=r"(r1), "=r"(r2), "=r"(r3) : "r"(addr));
}
__device__ __forceinline__ void mma_bf16(float& d0, float& d1, float& d2, float& d3,
                                         uint32_t a0, uint32_t a1, uint32_t a2,
                                         uint32_t a3, uint32_t b0, uint32_t b1) {
    asm volatile(
        "mma.sync.aligned.m16n8k16.row.col.f32.bf16.bf16.f32 "
        "{%0,%1,%2,%3}, {%4,%5,%6,%7}, {%8,%9}, {%0,%1,%2,%3};"
        : "+f"(d0), "+f"(d1), "+f"(d2), "+f"(d3)
        : "r"(a0), "r"(a1), "r"(a2), "r"(a3), "r"(b0), "r"(b1));
}

// ---------------------------------------------------------------------------
// Kernel 1: xp = x + 0.5*(pos32[8n+3] + pos32[8n+4]); write A' = [h | l]
// ---------------------------------------------------------------------------
__global__ __launch_bounds__(256) void pos_add_split_kernel(
    const float* __restrict__ x, const float* __restrict__ pos32,
    __nv_bfloat16* __restrict__ x2)
{
    int idx = blockIdx.x * blockDim.x + threadIdx.x;  // float4 index over [M,512]
    int c4 = idx & (CC / 4 - 1);
    int bn = idx >> 7;
    int n  = bn & (NN - 1);

    float4 xv = reinterpret_cast<const float4*>(x)[idx];
    const float4* p = reinterpret_cast<const float4*>(pos32) +
                      (size_t)(8 * n + 3) * (CC / 4) + c4;
    float4 a = p[0];
    float4 b = p[CC / 4];
    float v0 = xv.x + 0.5f * (a.x + b.x);
    float v1 = xv.y + 0.5f * (a.y + b.y);
    float v2 = xv.z + 0.5f * (a.z + b.z);
    float v3 = xv.w + 0.5f * (a.w + b.w);

    __nv_bfloat162 h01 = __nv_bfloat162(__float2bfloat16(v0), __float2bfloat16(v1));
    __nv_bfloat162 h23 = __nv_bfloat162(__float2bfloat16(v2), __float2bfloat16(v3));
    __nv_bfloat162 l01 = __nv_bfloat162(
        __float2bfloat16(v0 - __bfloat162float(h01.x)),
        __float2bfloat16(v1 - __bfloat162float(h01.y)));
    __nv_bfloat162 l23 = __nv_bfloat162(
        __float2bfloat16(v2 - __bfloat162float(h23.x)),
        __float2bfloat16(v3 - __bfloat162float(h23.y)));

    __nv_bfloat162* o = reinterpret_cast<__nv_bfloat162*>(x2);
    const size_t rb = (size_t)bn * (KST / 2);  // row base in bf162 units (512)
    const int cc = c4 * 2;
    o[rb + cc]           = h01;  o[rb + cc + 1]       = h23;   // block 0: hi
    o[rb + 256 + cc]     = l01;  o[rb + 256 + cc + 1] = l23;   // block 1: lo
}

// ---------------------------------------------------------------------------
// Kernel 2: weight prep — w[k][n] fp32 -> B'[n][1024] = [h | l]
// ---------------------------------------------------------------------------
__global__ __launch_bounds__(256) void wprep_kernel(
    const float* __restrict__ w, __nv_bfloat16* __restrict__ w2, int Nw)
{
    int idx = blockIdx.x * blockDim.x + threadIdx.x;  // = k*Nw + n (coalesced read)
    int k = idx / Nw;
    int n = idx - k * Nw;
    float v = w[idx];
    __nv_bfloat16 h = __float2bfloat16(v);
    __nv_bfloat16 l = __float2bfloat16(v - __bfloat162float(h));
    __nv_bfloat16* row = w2 + (size_t)n * KST;
    row[k]       = h;
    row[512 + k] = l;
}

// ---------------------------------------------------------------------------
// Kernel 3: bf16 tensor-core GEMM (mma.sync).
//   C[M,N] = Ah@Bh^T + Ah@Bl^T + Al@Bh^T + bias   (A',B' stored [h|l], K=1024)
//   24 compute stages of K=64: s<8 -> (h,h), s<16 -> (h,l), s<24 -> (l,h).
//   CTA 128x128, 8 warps @ 64x32, cp.async 3-stage, 2 CTAs/SM.
// ---------------------------------------------------------------------------
#define GBK 64
#define NSTAGE 24
#define TILE_BYTES (128 * 128)            // 128 rows x 64 bf16 = 16 KB
#define STAGE_BYTES (2 * TILE_BYTES)      // A tile + B tile
#define GEMM_SMEM (1024 + 3 * STAGE_BYTES)

__global__ void __launch_bounds__(256, 2) gemm_mma_kernel(
    const __nv_bfloat16* __restrict__ A2, const __nv_bfloat16* __restrict__ B2,
    const float* __restrict__ bias, float* __restrict__ C, int N)
{
    extern __shared__ char dsm[];
    uint32_t raw = smem_u32(dsm);
    uint32_t pad = (1024u - (raw & 1023u)) & 1023u;
    const uint32_t sb = raw + pad;

    const int tid  = threadIdx.x;
    const int wid  = tid >> 5;
    const int lane = tid & 31;
    const int wm = wid & 1;        // 2 warps along M (64 each)
    const int wn = wid >> 1;       // 4 warps along N (32 each)
    const int bx = blockIdx.x;     // N tile
    const int by = blockIdx.y;     // M tile

    const __nv_bfloat16* ga0 = A2 + (size_t)(by * 128) * KST;
    const __nv_bfloat16* gb0 = B2 + (size_t)(bx * 128) * KST;

    // stage s -> K-chunk offsets into the [h|l] storage
    auto load_stage = [&](int s) {
        const int buf = s % 3;
        const int ao = (s < 8 ? s : s - 8) * GBK;
        const int bo = (s < 16 ? s : s - 16) * GBK;
        const __nv_bfloat16* ga = ga0 + ao;
        const __nv_bfloat16* gb = gb0 + bo;
        const uint32_t as = sb + 1024 + buf * STAGE_BYTES;
        const uint32_t bs = as + TILE_BYTES;
#pragma unroll
        for (int i = 0; i < 4; ++i) {
            const int q = i * 256 + tid;
            const int r = q >> 3, c = q & 7;
            const uint32_t off = r * 128 + ((c ^ (r & 7)) << 4);
            cp16(as + off, ga + (size_t)r * KST + c * 8);
            cp16(bs + off, gb + (size_t)r * KST + c * 8);
        }
    };

    float acc[4][4][4];
#pragma unroll
    for (int mi = 0; mi < 4; ++mi)
#pragma unroll
        for (int ni = 0; ni < 4; ++ni)
#pragma unroll
            for (int e = 0; e < 4; ++e) acc[mi][ni][e] = 0.f;

    load_stage(0); CP_COMMIT();
    load_stage(1); CP_COMMIT();

    for (int s = 0; s < NSTAGE; ++s) {
        if (s + 2 < NSTAGE) { CP_WAIT(1); } else { CP_WAIT(0); }
        __syncthreads();
        if (s + 2 < NSTAGE) { load_stage(s + 2); CP_COMMIT(); }

        const int buf = s % 3;
        const uint32_t asw = sb + 1024 + buf * STAGE_BYTES;
        const uint32_t bsw = asw + TILE_BYTES;

#pragma unroll
        for (int ks = 0; ks < 4; ++ks) {
            uint32_t af[4][4];
#pragma unroll
            for (int mi = 0; mi < 4; ++mi) {
                const int row = wm * 64 + mi * 16 + (lane & 15);
                const int ch  = ks * 2 + (lane >> 4);
                ldsm_x4(af[mi][0], af[mi][1], af[mi][2], af[mi][3],
                        asw + row * 128 + ((ch ^ (row & 7)) << 4));
            }
            uint32_t bf[2][4];
#pragma unroll
            for (int nj = 0; nj < 2; ++nj) {
                const int row = wn * 32 + nj * 16 + (lane & 7) + ((lane >> 4) & 1) * 8;
                const int ch  = ks * 2 + ((lane >> 3) & 1);
                ldsm_x4(bf[nj][0], bf[nj][1], bf[nj][2], bf[nj][3],
                        bsw + row * 128 + ((ch ^ (row & 7)) << 4));
            }
#pragma unroll
            for (int mi = 0; mi < 4; ++mi)
#pragma unroll
                for (int ni = 0; ni < 4; ++ni) {
                    const uint32_t* bp = &bf[ni >> 1][(ni & 1) * 2];
                    mma_bf16(acc[mi][ni][0], acc[mi][ni][1],
                             acc[mi][ni][2], acc[mi][ni][3],
                             af[mi][0], af[mi][1], af[mi][2], af[mi][3],
                             bp[0], bp[1]);
                }
        }
    }

    // epilogue: d0,d1 -> (row, col..col+1); d2,d3 -> (row+8, col..col+1)
    const int rbase = by * 128 + wm * 64 + (lane >> 2);
    const int cbase = bx * 128 + wn * 32 + (lane & 3) * 2;
#pragma unroll
    for (int mi = 0; mi < 4; ++mi) {
#pragma unroll
        for (int ni = 0; ni < 4; ++ni) {
            const int r = rbase + mi * 16;
            const int c = cbase + ni * 8;
            const float2 bv = *reinterpret_cast<const float2*>(bias + c);
            float2 o0, o1;
            o0.x = acc[mi][ni][0] + bv.x;
            o0.y = acc[mi][ni][1] + bv.y;
            o1.x = acc[mi][ni][2] + bv.x;
            o1.y = acc[mi][ni][3] + bv.y;
            *reinterpret_cast<float2*>(C + (size_t)r * N + c) = o0;
            *reinterpret_cast<float2*>(C + (size_t)(r + 8) * N + c) = o1;
        }
    }
}

// ---------------------------------------------------------------------------
// Kernel 4: per-token attention over heads; ctx written as A' = [h | l]
// in transposed layout: row (b*4096 + h*512 + n/8), col (n%8)*64 + d.
// ---------------------------------------------------------------------------
#define QK_PITCH 68

__global__ __launch_bounds__(256) void attn_kernel(
    const float* __restrict__ qkv, __nv_bfloat16* __restrict__ c2)
{
    __shared__ float qs[8][NH * QK_PITCH];
    __shared__ float ks[8][NH * QK_PITCH];
    __shared__ float ps[8][NH * NH];

    const int warp = threadIdx.x >> 5;
    const int lane = threadIdx.x & 31;
    const int token = blockIdx.x * 8 + warp;
    const int b = token >> 12;
    const int n = token & (NN - 1);

    const float* base = qkv + (size_t)token * QKV_N;
    float* const qw = qs[warp];
    float* const kw = ks[warp];
    float* const pw = ps[warp];

#pragma unroll
    for (int it = 0; it < 16; ++it) {
        const int idx = lane + it * 32;
        const int r = idx >> 6, t = idx & 63;
        qw[r * QK_PITCH + t] = base[idx];
        kw[r * QK_PITCH + t] = base[512 + idx];
    }
    __syncwarp();

    const int i0 = lane >> 3;
    const int j0 = lane & 7;
    const float* qr0 = qw + i0 * QK_PITCH;
    const float* qr1 = qr0 + 4 * QK_PITCH;
    const float* kr  = kw + j0 * QK_PITCH;
    float s0 = 0.f, s1 = 0.f;
#pragma unroll
    for (int t = 0; t < HD; ++t) {
        const float kv = kr[t];
        s0 = fmaf(qr0[t], kv, s0);
        s1 = fmaf(qr1[t], kv, s1);
    }
    s0 *= 0.125f;
    s1 *= 0.125f;

    float m0 = s0, m1 = s1;
#pragma unroll
    for (int off = 1; off < 8; off <<= 1) {
        m0 = fmaxf(m0, __shfl_xor_sync(0xffffffffu, m0, off));
        m1 = fmaxf(m1, __shfl_xor_sync(0xffffffffu, m1, off));
    }
    float p0 = __expf(s0 - m0);
    float p1 = __expf(s1 - m1);
    float sum0 = p0, sum1 = p1;
#pragma unroll
    for (int off = 1; off < 8; off <<= 1) {
        sum0 += __shfl_xor_sync(0xffffffffu, sum0, off);
        sum1 += __shfl_xor_sync(0xffffffffu, sum1, off);
    }
    pw[i0 * 8 + j0] = p0 / sum0;
    pw[(i0 + 4) * 8 + j0] = p1 / sum1;
    __syncwarp();

    const float* vbase = base + 1024;
    const int nlo = n >> 3;
    const int csub = (n & 7) * HD;
#pragma unroll
    for (int dd = 0; dd < 2; ++dd) {
        const int d = lane + dd * 32;
        float vv[NH];
#pragma unroll
        for (int j = 0; j < NH; ++j) vv[j] = vbase[j * HD + d];
#pragma unroll
        for (int i = 0; i < NH; ++i) {
            float o = 0.f;
#pragma unroll
            for (int j = 0; j < NH; ++j) o = fmaf(pw[i * 8 + j], vv[j], o);
            const size_t row = (size_t)b * NN + i * 512 + nlo;
            const size_t addr = row * KST + csub + d;
            __nv_bfloat16 h = __float2bfloat16(o);
            c2[addr]       = h;
            c2[addr + 512] = __float2bfloat16(o - __bfloat162float(h));
        }
    }
}

// ---------------------------------------------------------------------------
// Launch
// ---------------------------------------------------------------------------
extern "C" void kernel_launch(void* const* d_in, const int* in_sizes, int n_in,
                              void* d_out, int out_size)
{
    const float* x      = (const float*)d_in[0];
    const float* pos32  = (const float*)d_in[1];
    const float* w_qkv  = (const float*)d_in[2];
    const float* b_qkv  = (const float*)d_in[3];
    const float* w_proj = (const float*)d_in[4];
    const float* b_proj = (const float*)d_in[5];
    float* out = (float*)d_out;

    __nv_bfloat16 *x2, *c2, *wq2, *wp2;
    float* qkv;
    cudaGetSymbolAddress((void**)&x2,  g_x2);
    cudaGetSymbolAddress((void**)&qkv, g_qkv);
    cudaGetSymbolAddress((void**)&c2,  g_c2);
    cudaGetSymbolAddress((void**)&wq2, g_wq2);
    cudaGetSymbolAddress((void**)&wp2, g_wp2);

    cudaFuncSetAttribute(gemm_mma_kernel,
                         cudaFuncAttributeMaxDynamicSharedMemorySize, GEMM_SMEM);

    // 1) pos interp + add, split into [h|l] layout
    pos_add_split_kernel<<<M_TOT * CC / 4 / 256, 256>>>(x, pos32, x2);
    // 2) weight prep: [512,Nw] fp32 -> [Nw,1024] bf16 [h|l]
    wprep_kernel<<<(CC * QKV_N) / 256, 256>>>(w_qkv, wq2, QKV_N);
    wprep_kernel<<<(CC * CC) / 256, 256>>>(w_proj, wp2, CC);
    // 3) QKV GEMM (tensor cores) -> fp32
    {
        dim3 grid(QKV_N / 128, M_TOT / 128);
        gemm_mma_kernel<<<grid, 256, GEMM_SMEM>>>(x2, wq2, b_qkv, qkv, QKV_N);
    }
    // 4) attention; ctx emitted in [h|l] layout for proj
    attn_kernel<<<M_TOT / 8, 256>>>(qkv, c2);
    // 5) proj GEMM (tensor cores) -> out
    {
        dim3 grid(CC / 128, M_TOT / 128);
        gemm_mma_kernel<<<grid, 256, GEMM_SMEM>>>(c2, wp2, b_proj, out, CC);
    }
}